// round 12
// baseline (speedup 1.0000x reference)
#include <cuda_runtime.h>
#include <math_constants.h>

// x:    (16, 64, 512, 512) float32
// mask: (16, 1, 512, 512) int32
// out:  (16, 64) float32
#define NB 16
#define NC 64
#define HW (512 * 512)                 // 262144
#define CHUNKS 16                      // chunks per (b,c) row
#define THREADS 256
#define CG 2                           // channels per block
#define F4_PER_CHUNK (HW / 4 / CHUNKS) // 4096 float4 per chunk
#define ITERS (F4_PER_CHUNK / THREADS) // 16 float4 per thread per channel
#define NROWS (NB * NC)                // 1024
#define NGRP (NB * (NC / CG))          // 512 row-groups

// Scratch: g_partial fully overwritten each launch; g_ctr self-resetting;
// g_nonempty monotone OR of input-determined value => graph-replay safe.
__device__ float g_partial[NROWS * CHUNKS];
__device__ int   g_ctr[NGRP];
__device__ int   g_nonempty[NB];

__global__ void __launch_bounds__(THREADS)
fused_kernel(const float4* __restrict__ x, const int4* __restrict__ mask4,
             float* __restrict__ out) {
    int blk  = blockIdx.x;              // = (b*(NC/CG) + cg)*16 + chunk
    int t    = threadIdx.x;
    int lane = t & 31;
    int wid  = t >> 5;

    int chunk = blk & (CHUNKS - 1);
    int grp   = blk >> 4;               // b*(NC/CG) + cg
    int b     = grp >> 5;               // / (NC/CG) = /32
    int cg    = grp & (NC / CG - 1);
    int rowbase = b * NC + cg * CG;

    __shared__ float smax[CG * (THREADS / 32)];
    __shared__ bool  slast;

    // ---- Private mask pack: this thread's 64 positions -> 2 registers ----
    const int4* mr = mask4 + (size_t)b * (HW / 4)
                           + (size_t)chunk * F4_PER_CHUNK;
    unsigned bits0 = 0, bits1 = 0;
#pragma unroll
    for (int i = 0; i < ITERS; i++) {
        int4 mv = __ldg(mr + i * THREADS + t);
        unsigned nib = (unsigned)(mv.x != 0)
                     | ((unsigned)(mv.y != 0) << 1)
                     | ((unsigned)(mv.z != 0) << 2)
                     | ((unsigned)(mv.w != 0) << 3);
        if (i < 8) bits0 |= nib << (4 * i);
        else       bits1 |= nib << (4 * (i - 8));
    }
    int bany = __syncthreads_or((int)((bits0 | bits1) != 0));
    if (t == 0 && bany) atomicOr(&g_nonempty[b], 1);

    // ---- Stream CG channels, j-inner for load batching ----
    const float4* xb = x + (size_t)rowbase * (HW / 4)
                         + (size_t)chunk * F4_PER_CHUNK;
    float acc0 = -CUDART_INF_F, acc1 = -CUDART_INF_F;
#pragma unroll 4
    for (int i = 0; i < ITERS; i++) {
        unsigned nib = ((i < 8) ? (bits0 >> (4 * i))
                                : (bits1 >> (4 * (i - 8)))) & 0xFu;
        int idx = i * THREADS + t;
        float4 x0 = __ldg(xb + 0 * (HW / 4) + idx);
        float4 x1 = __ldg(xb + 1 * (HW / 4) + idx);
        bool m0 = nib & 1u, m1 = nib & 2u, m2 = nib & 4u, m3 = nib & 8u;
        acc0 = fmaxf(acc0, m0 ? x0.x : -CUDART_INF_F);
        acc0 = fmaxf(acc0, m1 ? x0.y : -CUDART_INF_F);
        acc0 = fmaxf(acc0, m2 ? x0.z : -CUDART_INF_F);
        acc0 = fmaxf(acc0, m3 ? x0.w : -CUDART_INF_F);
        acc1 = fmaxf(acc1, m0 ? x1.x : -CUDART_INF_F);
        acc1 = fmaxf(acc1, m1 ? x1.y : -CUDART_INF_F);
        acc1 = fmaxf(acc1, m2 ? x1.z : -CUDART_INF_F);
        acc1 = fmaxf(acc1, m3 ? x1.w : -CUDART_INF_F);
    }

    // ---- Warp reduce each channel accumulator (full warps: full mask OK) ----
    float a[CG] = {acc0, acc1};
#pragma unroll
    for (int j = 0; j < CG; j++) {
        float v = a[j];
#pragma unroll
        for (int o = 16; o; o >>= 1)
            v = fmaxf(v, __shfl_xor_sync(0xffffffffu, v, o));
        if (lane == 0) smax[j * (THREADS / 32) + wid] = v;
    }
    __syncthreads();

    // ---- Per-block: 16 threads reduce 8 warp-partials per channel ----
    // NOTE: only 16 lanes execute this -> mask MUST be 0xffff, not full.
    if (t < CG * (THREADS / 32)) {      // 16 threads: j = t>>3, warp w = t&7
        float v = smax[t];
#pragma unroll
        for (int o = 4; o; o >>= 1)
            v = fmaxf(v, __shfl_xor_sync(0xffffu, v, o));
        if ((t & 7) == 0)
            g_partial[(rowbase + (t >> 3)) * CHUNKS + chunk] = v;
    }
    __threadfence();
    __syncthreads();

    if (t == 0) {
        int old = atomicAdd(&g_ctr[grp], 1);
        slast = (old == CHUNKS - 1);
    }
    __syncthreads();

    // ---- Last block of the row-group: 32 threads (full warp) reduce ----
    if (slast && t < CG * CHUNKS) {     // 32 threads: j = t>>4, k = t&15
        int j = t >> 4;
        float v = g_partial[(rowbase + j) * CHUNKS + (t & 15)];
#pragma unroll
        for (int o = 8; o; o >>= 1)
            v = fmaxf(v, __shfl_xor_sync(0xffffffffu, v, o));
        if ((t & 15) == 0)
            out[rowbase + j] = g_nonempty[b] ? v : 0.0f;
        if (t == 0) g_ctr[grp] = 0;     // reset for next graph replay
    }
}

extern "C" void kernel_launch(void* const* d_in, const int* in_sizes, int n_in,
                              void* d_out, int out_size) {
    const float4* x     = (const float4*)d_in[0];
    const int4*   mask4 = (const int4*)d_in[1];
    float*        out   = (float*)d_out;

    fused_kernel<<<NB * (NC / CG) * CHUNKS, THREADS>>>(x, mask4, out);
}

// round 13
// speedup vs baseline: 1.0045x; 1.0045x over previous
#include <cuda_runtime.h>
#include <math_constants.h>

// x:    (16, 64, 512, 512) float32
// mask: (16, 1, 512, 512) int32
// out:  (16, 64) float32
#define NB 16
#define NC 64
#define HW (512 * 512)                 // 262144
#define CHUNKS 16                      // chunks per (b,c) row
#define THREADS 256
#define CG 2                           // channels per block
#define F4_PER_CHUNK (HW / 4 / CHUNKS) // 4096 float4 per chunk
#define ITERS (F4_PER_CHUNK / THREADS) // 16 float4 per thread per channel
#define NROWS (NB * NC)                // 1024
#define NGRP (NB * (NC / CG))          // 512 row-groups

// Scratch: g_partial fully overwritten each launch; g_ctr self-resetting;
// g_nonempty monotone OR of input-determined value => graph-replay safe.
__device__ float g_partial[NROWS * CHUNKS];
__device__ int   g_ctr[NGRP];
__device__ int   g_nonempty[NB];

__global__ void __launch_bounds__(THREADS)
fused_kernel(const float4* __restrict__ x, const int4* __restrict__ mask4,
             float* __restrict__ out) {
    int blk  = blockIdx.x;              // = (b*(NC/CG) + cg)*16 + chunk
    int t    = threadIdx.x;
    int lane = t & 31;
    int wid  = t >> 5;

    int chunk = blk & (CHUNKS - 1);
    int grp   = blk >> 4;               // b*(NC/CG) + cg
    int b     = grp >> 5;               // / (NC/CG) = /32
    int cg    = grp & (NC / CG - 1);
    int rowbase = b * NC + cg * CG;

    __shared__ float smax[CG * (THREADS / 32)];
    __shared__ int   sany[THREADS / 32];
    __shared__ bool  slast;

    // ---- Private mask pack: this thread's 64 positions -> 2 registers ----
    // NO barrier here: x loads below are independent and can overlap these.
    const int4* mr = mask4 + (size_t)b * (HW / 4)
                           + (size_t)chunk * F4_PER_CHUNK;
    unsigned bits0 = 0, bits1 = 0;
#pragma unroll
    for (int i = 0; i < ITERS; i++) {
        int4 mv = __ldg(mr + i * THREADS + t);
        unsigned nib = (unsigned)(mv.x != 0)
                     | ((unsigned)(mv.y != 0) << 1)
                     | ((unsigned)(mv.z != 0) << 2)
                     | ((unsigned)(mv.w != 0) << 3);
        if (i < 8) bits0 |= nib << (4 * i);
        else       bits1 |= nib << (4 * (i - 8));
    }
    // Warp-level any (full warp active -> full mask legal); published by the
    // post-stream __syncthreads below, consumed by t==0 after it.
    unsigned wany = __ballot_sync(0xffffffffu, (bits0 | bits1) != 0);
    if (lane == 0) sany[wid] = (wany != 0);

    // ---- Stream CG channels, j-inner for load batching ----
    const float4* xb = x + (size_t)rowbase * (HW / 4)
                         + (size_t)chunk * F4_PER_CHUNK;
    float acc0 = -CUDART_INF_F, acc1 = -CUDART_INF_F;
#pragma unroll 4
    for (int i = 0; i < ITERS; i++) {
        unsigned nib = ((i < 8) ? (bits0 >> (4 * i))
                                : (bits1 >> (4 * (i - 8)))) & 0xFu;
        int idx = i * THREADS + t;
        float4 x0 = __ldg(xb + 0 * (HW / 4) + idx);
        float4 x1 = __ldg(xb + 1 * (HW / 4) + idx);
        bool m0 = nib & 1u, m1 = nib & 2u, m2 = nib & 4u, m3 = nib & 8u;
        acc0 = fmaxf(acc0, m0 ? x0.x : -CUDART_INF_F);
        acc0 = fmaxf(acc0, m1 ? x0.y : -CUDART_INF_F);
        acc0 = fmaxf(acc0, m2 ? x0.z : -CUDART_INF_F);
        acc0 = fmaxf(acc0, m3 ? x0.w : -CUDART_INF_F);
        acc1 = fmaxf(acc1, m0 ? x1.x : -CUDART_INF_F);
        acc1 = fmaxf(acc1, m1 ? x1.y : -CUDART_INF_F);
        acc1 = fmaxf(acc1, m2 ? x1.z : -CUDART_INF_F);
        acc1 = fmaxf(acc1, m3 ? x1.w : -CUDART_INF_F);
    }

    // ---- Warp reduce each channel accumulator (full warps: full mask OK) ----
    float a[CG] = {acc0, acc1};
#pragma unroll
    for (int j = 0; j < CG; j++) {
        float v = a[j];
#pragma unroll
        for (int o = 16; o; o >>= 1)
            v = fmaxf(v, __shfl_xor_sync(0xffffffffu, v, o));
        if (lane == 0) smax[j * (THREADS / 32) + wid] = v;
    }
    __syncthreads();                    // publishes smax AND sany

    if (t == 0) {
        int any = 0;
#pragma unroll
        for (int w = 0; w < THREADS / 32; w++) any |= sany[w];
        if (any) atomicOr(&g_nonempty[b], 1);
    }

    // ---- Per-block: 16 threads reduce 8 warp-partials per channel ----
    // Only 16 lanes execute -> partial mask 0xffff (all participants masked).
    if (t < CG * (THREADS / 32)) {      // 16 threads: j = t>>3, warp w = t&7
        float v = smax[t];
#pragma unroll
        for (int o = 4; o; o >>= 1)
            v = fmaxf(v, __shfl_xor_sync(0xffffu, v, o));
        if ((t & 7) == 0)
            g_partial[(rowbase + (t >> 3)) * CHUNKS + chunk] = v;
    }
    __threadfence();
    __syncthreads();

    if (t == 0) {
        int old = atomicAdd(&g_ctr[grp], 1);
        slast = (old == CHUNKS - 1);
    }
    __syncthreads();

    // ---- Last block of the row-group: 32 threads (full warp) reduce ----
    if (slast && t < CG * CHUNKS) {     // 32 threads: j = t>>4, k = t&15
        int j = t >> 4;
        float v = g_partial[(rowbase + j) * CHUNKS + (t & 15)];
#pragma unroll
        for (int o = 8; o; o >>= 1)
            v = fmaxf(v, __shfl_xor_sync(0xffffffffu, v, o));
        if ((t & 15) == 0)
            out[rowbase + j] = g_nonempty[b] ? v : 0.0f;
        if (t == 0) g_ctr[grp] = 0;     // reset for next graph replay
    }
}

extern "C" void kernel_launch(void* const* d_in, const int* in_sizes, int n_in,
                              void* d_out, int out_size) {
    const float4* x     = (const float4*)d_in[0];
    const int4*   mask4 = (const int4*)d_in[1];
    float*        out   = (float*)d_out;

    fused_kernel<<<NB * (NC / CG) * CHUNKS, THREADS>>>(x, mask4, out);
}

// round 14
// speedup vs baseline: 1.0462x; 1.0415x over previous
#include <cuda_runtime.h>
#include <math_constants.h>

// x:    (16, 64, 512, 512) float32
// mask: (16, 1, 512, 512) int32
// out:  (16, 64) float32
#define NB 16
#define NC 64
#define HW (512 * 512)                 // 262144
#define CHUNKS 16                      // chunks per (b,c) row
#define THREADS 256
#define F4_PER_CHUNK (HW / 4 / CHUNKS) // 4096 float4 per chunk
#define ITERS (F4_PER_CHUNK / THREADS) // 16 float4 per thread
#define NROWS (NB * NC)                // 1024
#define NCID (NB * CHUNKS)             // 256 (b,chunk) pairs

// Bitmask: uint2 per (cid, thread): thread-private nibble order.
// bits0 nibble i (i<8) / bits1 nibble i-8 cover float4 idx = i*256 + t.
__device__ uint2 g_bits2[NCID * THREADS];       // 512 KiB, overwritten each launch
__device__ int   g_nonempty[NB];                // 0-init; monotone OR, replay-safe
__device__ float g_partial[NROWS * CHUNKS];     // overwritten each launch
__device__ int   g_ctr[NROWS];                  // self-resetting

// ---- Pack: one block per (b,chunk); thread packs its own 64 positions ----
__global__ void __launch_bounds__(THREADS)
pack_kernel(const int4* __restrict__ mask4) {
    int cid   = blockIdx.x;             // b*CHUNKS + chunk
    int b     = cid >> 4;
    int chunk = cid & (CHUNKS - 1);
    int t     = threadIdx.x;

    const int4* mr = mask4 + (size_t)b * (HW / 4)
                           + (size_t)chunk * F4_PER_CHUNK;
    unsigned bits0 = 0, bits1 = 0;
#pragma unroll
    for (int i = 0; i < ITERS; i++) {
        int4 mv = __ldg(mr + i * THREADS + t);
        unsigned nib = (unsigned)(mv.x != 0)
                     | ((unsigned)(mv.y != 0) << 1)
                     | ((unsigned)(mv.z != 0) << 2)
                     | ((unsigned)(mv.w != 0) << 3);
        if (i < 8) bits0 |= nib << (4 * i);
        else       bits1 |= nib << (4 * (i - 8));
    }
    g_bits2[cid * THREADS + t] = make_uint2(bits0, bits1);

    int bany = __syncthreads_or((int)((bits0 | bits1) != 0));
    if (t == 0 && bany) atomicOr(&g_nonempty[b], 1);
}

// ---- Pool: one block per (row, chunk); mask = one 8B load per thread ----
__global__ void __launch_bounds__(THREADS)
pool_kernel(const float4* __restrict__ x, float* __restrict__ out) {
    int blk   = blockIdx.x;
    int chunk = blk & (CHUNKS - 1);
    int row   = blk >> 4;               // b*NC + c
    int b     = row >> 6;
    int cid   = b * CHUNKS + chunk;
    int t     = threadIdx.x;
    int lane  = t & 31;

    uint2 bb = g_bits2[cid * THREADS + t];      // 8B coalesced, L2-resident
    unsigned bits0 = bb.x, bits1 = bb.y;

    const float4* xr = x + (size_t)row * (HW / 4) + (size_t)chunk * F4_PER_CHUNK;
    float vmax = -CUDART_INF_F;
#pragma unroll
    for (int i = 0; i < ITERS; i++) {
        unsigned nib = ((i < 8) ? (bits0 >> (4 * i))
                                : (bits1 >> (4 * (i - 8)))) & 0xFu;
        float4 xv = __ldg(xr + i * THREADS + t);
        vmax = fmaxf(vmax, (nib & 1u) ? xv.x : -CUDART_INF_F);
        vmax = fmaxf(vmax, (nib & 2u) ? xv.y : -CUDART_INF_F);
        vmax = fmaxf(vmax, (nib & 4u) ? xv.z : -CUDART_INF_F);
        vmax = fmaxf(vmax, (nib & 8u) ? xv.w : -CUDART_INF_F);
    }

#pragma unroll
    for (int o = 16; o; o >>= 1)
        vmax = fmaxf(vmax, __shfl_xor_sync(0xffffffffu, vmax, o));

    __shared__ float smax[THREADS / 32];
    __shared__ bool  slast;
    if (lane == 0) smax[t >> 5] = vmax;
    __syncthreads();

    if (t == 0) {
        float m = smax[0];
#pragma unroll
        for (int w = 1; w < THREADS / 32; w++) m = fmaxf(m, smax[w]);
        g_partial[row * CHUNKS + chunk] = m;
        __threadfence();
        int old = atomicAdd(&g_ctr[row], 1);
        slast = (old == CHUNKS - 1);
    }
    __syncthreads();

    // Last block of this row: 16 threads reduce 16 partials (partial mask!),
    // apply empty-mask fixup, write out, reset counter for graph replay.
    if (slast && t < CHUNKS) {
        float v = g_partial[row * CHUNKS + t];
#pragma unroll
        for (int o = CHUNKS / 2; o; o >>= 1)
            v = fmaxf(v, __shfl_xor_sync(0xffffu, v, o));
        if (t == 0) {
            out[row] = g_nonempty[b] ? v : 0.0f;
            g_ctr[row] = 0;
        }
    }
}

extern "C" void kernel_launch(void* const* d_in, const int* in_sizes, int n_in,
                              void* d_out, int out_size) {
    const float4* x     = (const float4*)d_in[0];
    const int4*   mask4 = (const int4*)d_in[1];
    float*        out   = (float*)d_out;

    pack_kernel<<<NCID, THREADS>>>(mask4);
    pool_kernel<<<NROWS * CHUNKS, THREADS>>>(x, out);
}